// round 15
// baseline (speedup 1.0000x reference)
#include <cuda_runtime.h>
#include <cuda_bf16.h>
#include <cstdint>
#include <cmath>

static __device__ float g_scratch[28u * 1024u * 1024u];
static __device__ __nv_bfloat16 g_bf[119u * 1024u * 1024u];
static __device__ unsigned g_cnt;

#define OFF_EMB     ((size_t)0)
#define OFF_DEMB    (OFF_EMB    + 2048*512)
#define OFF_XP0F    (OFF_DEMB   + 2048*512)
#define OFF_XP0B    (OFF_XP0F   + 2048*2048)
#define OFF_XP      (OFF_XP0B   + 2048*2048)
#define OFF_OF      (OFF_XP     + 2048*2048)
#define OFF_OB      (OFF_OF     + 2048*512)
#define OFF_CAT     (OFF_OB     + 2048*512)
#define OFF_L1      (OFF_CAT    + 2048*1024)
#define OFF_L2      (OFF_L1     + 2048*512)
#define OFF_TOPCTX  (OFF_L2     + 2048*512)
#define OFF_H0      (OFF_TOPCTX + 2048*1024)
#define OFF_H1      (OFF_H0   + 16384)
#define OFF_CC      (OFF_H1   + 16384)
#define OFF_HB0     (OFF_CC   + 16384)
#define OFF_HB1     (OFF_HB0  + 16384)
#define OFF_CB      (OFF_HB1  + 16384)
#define OFF_DHA     (OFF_CB   + 16384)
#define OFF_DHB     (OFF_DHA  + 4*16384)
#define OFF_DC      (OFF_DHB  + 4*16384)
#define OFF_CTX     (OFF_DC   + 4*16384)
#define OFF_ENCA    (OFF_CTX  + 16384)
#define OFF_AWT     (OFF_ENCA + 2048*512)
#define OFF_DEMBXP  (OFF_AWT  + 512*512)
#define OFF_END     (OFF_DEMBXP + 2048*2048)
static_assert(OFF_END <= (size_t)28u * 1024u * 1024u, "scratch overflow");

#define BF_W   ((size_t)0)
#define BF_A   (BF_W  + (size_t)32000 * 3072)
#define BF_XA  (BF_A  + (size_t)2048 * 3072)
#define BF_XW  (BF_XA + (size_t)2048 * 1536)
#define BF_CT  (BF_XW + (size_t)2048 * 1536)
#define BF_PW  (BF_CT + (size_t)2048 * 3072)
#define BF_END (BF_PW + (size_t)512 * 3072)
static_assert(BF_END <= (size_t)119u * 1024u * 1024u, "bf overflow");

__device__ __forceinline__ float warp_sum(float v) {
#pragma unroll
    for (int o = 16; o > 0; o >>= 1) v += __shfl_xor_sync(0xffffffffu, v, o);
    return v;
}
__device__ __forceinline__ float sigf(float x) { return 1.f / (1.f + expf(-x)); }
__device__ __forceinline__ uint32_t smem_u32(const void* p) {
    uint32_t a;
    asm("{ .reg .u64 t; cvta.to.shared.u64 t, %1; cvt.u32.u64 %0, t; }" : "=r"(a) : "l"(p));
    return a;
}
__device__ __forceinline__ void cp16(uint32_t d, const void* g) {
    asm volatile("cp.async.cg.shared.global [%0], [%1], 16;" :: "r"(d), "l"(g));
}
__device__ __forceinline__ void gsync(unsigned target) {
    __syncthreads();
    __threadfence();
    if (threadIdx.x == 0) {
        atomicAdd(&g_cnt, 1u);
        volatile unsigned* p = &g_cnt;
        while (*p < target) {}
        __threadfence();
    }
    __syncthreads();
}

__global__ void embed_kernel(const int* __restrict__ tok, const float* __restrict__ tab,
                             float* __restrict__ out, int total) {
    int idx = blockIdx.x * 256 + threadIdx.x;
    if (idx >= total) return;
    int row = idx >> 9, col = idx & 511;
    int t = tok[row];
    out[idx] = (t == 0) ? 0.f : tab[(size_t)t * 512 + col];
}
__global__ void concat2_kernel(float* __restrict__ dst, const float* __restrict__ a,
                               const float* __restrict__ b, int total) {
    int idx = blockIdx.x * 256 + threadIdx.x;
    if (idx >= total) return;
    int r = idx >> 10, cidx = idx & 1023;
    dst[idx] = (cidx < 512) ? a[r * 512 + cidx] : b[r * 512 + cidx - 512];
}
__global__ void add2_kernel(float* __restrict__ d, const float* __restrict__ a,
                            const float* __restrict__ b, int n) {
    int i = blockIdx.x * 256 + threadIdx.x;
    if (i < n) d[i] = a[i] + b[i];
}
__global__ void addip_kernel(float* __restrict__ d, const float* __restrict__ a, int n) {
    int i = blockIdx.x * 256 + threadIdx.x;
    if (i < n) d[i] += a[i];
}
__global__ void transpose512_kernel(const float* __restrict__ in, float* __restrict__ out) {
    int idx = blockIdx.x * 256 + threadIdx.x;
    int r = idx >> 9, c = idx & 511;
    out[(size_t)c * 512 + r] = in[idx];
}

// ---- vectorized split kernels: each thread handles a float4 quad ----
__device__ __forceinline__ void split4(float4 v, uint2& hiq, uint2& loq) {
    __nv_bfloat16 h0 = __float2bfloat16(v.x), h1 = __float2bfloat16(v.y);
    __nv_bfloat16 h2 = __float2bfloat16(v.z), h3 = __float2bfloat16(v.w);
    __nv_bfloat16 l0 = __float2bfloat16(v.x - __bfloat162float(h0));
    __nv_bfloat16 l1 = __float2bfloat16(v.y - __bfloat162float(h1));
    __nv_bfloat16 l2 = __float2bfloat16(v.z - __bfloat162float(h2));
    __nv_bfloat16 l3 = __float2bfloat16(v.w - __bfloat162float(h3));
    __nv_bfloat162 hp0 = __nv_bfloat162(h0, h1), hp1 = __nv_bfloat162(h2, h3);
    __nv_bfloat162 lp0 = __nv_bfloat162(l0, l1), lp1 = __nv_bfloat162(l2, l3);
    hiq.x = *(uint32_t*)&hp0; hiq.y = *(uint32_t*)&hp1;
    loq.x = *(uint32_t*)&lp0; loq.y = *(uint32_t*)&lp1;
}
__global__ void split_w_g(const float* __restrict__ in, __nv_bfloat16* __restrict__ out,
                          int K, int lds, long rows) {
    long idx = (long)blockIdx.x * 256 + threadIdx.x;
    int qpr = K >> 2;
    if (idx >= rows * qpr) return;
    long r = idx / qpr; int k = (int)(idx - r * qpr) * 4;
    float4 v = *(const float4*)(in + r * lds + k);
    uint2 hiq, loq;
    split4(v, hiq, loq);
    size_t base = (size_t)r * 3 * K;
    *(uint2*)(out + base + k) = hiq;
    *(uint2*)(out + base + K + k) = hiq;
    *(uint2*)(out + base + 2 * K + k) = loq;
}
__global__ void split_a_g(const float* __restrict__ in, __nv_bfloat16* __restrict__ out,
                          int K, int lds, long rows) {
    long idx = (long)blockIdx.x * 256 + threadIdx.x;
    int qpr = K >> 2;
    if (idx >= rows * qpr) return;
    long r = idx / qpr; int k = (int)(idx - r * qpr) * 4;
    float4 v = *(const float4*)(in + r * lds + k);
    uint2 hiq, loq;
    split4(v, hiq, loq);
    size_t base = (size_t)r * 3 * K;
    *(uint2*)(out + base + k) = hiq;
    *(uint2*)(out + base + K + k) = loq;
    *(uint2*)(out + base + 2 * K + k) = hiq;
}

// BN=128 mma (feedforward GEMMs) — R8 version.
__global__ __launch_bounds__(256) void mma_gemm(
    const __nv_bfloat16* __restrict__ Abf, const __nv_bfloat16* __restrict__ Wbf,
    const float* __restrict__ bias, float* __restrict__ Cout,
    int Nout, int kchunks)
{
    extern __shared__ char dsm[];
    uint32_t sbase = smem_u32(dsm);
    uint32_t abase = (sbase + 1023u) & ~1023u;
    int tid = threadIdx.x;
    int wid = tid >> 5, lane = tid & 31;
    int wm = wid >> 2, wn = wid & 3;
    int mt = blockIdx.x, vt = blockIdx.y;
    int ld = kchunks * 64;
    const __nv_bfloat16* Arow = Abf + (size_t)mt * 128 * ld;
    const __nv_bfloat16* Wrow = Wbf + (size_t)vt * 128 * ld;
    float acc[4][4][4];
#pragma unroll
    for (int mi = 0; mi < 4; mi++)
#pragma unroll
        for (int ni = 0; ni < 4; ni++)
#pragma unroll
            for (int q = 0; q < 4; q++) acc[mi][ni][q] = 0.f;
    int lr = tid >> 3, lc16 = tid & 7;
    {
        uint32_t as = abase, bs = abase + 16384;
#pragma unroll
        for (int j = 0; j < 4; j++) {
            int r = lr + j * 32;
            uint32_t sw = ((uint32_t)(lc16 ^ (r & 7))) << 4;
            cp16(as + r * 128 + sw, Arow + (size_t)r * ld + lc16 * 8);
            cp16(bs + r * 128 + sw, Wrow + (size_t)r * ld + lc16 * 8);
        }
        asm volatile("cp.async.commit_group;");
    }
    for (int kc = 0; kc < kchunks; kc++) {
        int cur = kc & 1;
        if (kc < kchunks - 1) {
            uint32_t as = abase + (cur ^ 1) * 32768, bs = as + 16384;
            const __nv_bfloat16* Ak = Arow + (kc + 1) * 64;
            const __nv_bfloat16* Wk = Wrow + (kc + 1) * 64;
#pragma unroll
            for (int j = 0; j < 4; j++) {
                int r = lr + j * 32;
                uint32_t sw = ((uint32_t)(lc16 ^ (r & 7))) << 4;
                cp16(as + r * 128 + sw, Ak + (size_t)r * ld + lc16 * 8);
                cp16(bs + r * 128 + sw, Wk + (size_t)r * ld + lc16 * 8);
            }
            asm volatile("cp.async.commit_group;");
            asm volatile("cp.async.wait_group 1;");
        } else {
            asm volatile("cp.async.wait_group 0;");
        }
        __syncthreads();
        uint32_t as = abase + cur * 32768, bs = as + 16384;
#pragma unroll
        for (int ks = 0; ks < 4; ks++) {
            uint32_t a[4][4], b[4][2];
#pragma unroll
            for (int mi = 0; mi < 4; mi++) {
                int row = wm * 64 + mi * 16 + (lane & 15);
                int c16 = ks * 2 + (lane >> 4);
                uint32_t addr = as + row * 128 + (((uint32_t)(c16 ^ (row & 7))) << 4);
                asm volatile(
                    "ldmatrix.sync.aligned.m8n8.x4.shared.b16 {%0,%1,%2,%3}, [%4];"
                    : "=r"(a[mi][0]), "=r"(a[mi][1]), "=r"(a[mi][2]), "=r"(a[mi][3])
                    : "r"(addr));
            }
#pragma unroll
            for (int ni = 0; ni < 4; ni++) {
                int row = wn * 32 + ni * 8 + (lane & 7);
                int c16 = ks * 2 + ((lane >> 3) & 1);
                uint32_t addr = bs + row * 128 + (((uint32_t)(c16 ^ (row & 7))) << 4);
                asm volatile(
                    "ldmatrix.sync.aligned.m8n8.x2.shared.b16 {%0,%1}, [%2];"
                    : "=r"(b[ni][0]), "=r"(b[ni][1]) : "r"(addr));
            }
#pragma unroll
            for (int mi = 0; mi < 4; mi++)
#pragma unroll
                for (int ni = 0; ni < 4; ni++)
                    asm volatile(
                        "mma.sync.aligned.m16n8k16.row.col.f32.bf16.bf16.f32 "
                        "{%0,%1,%2,%3}, {%4,%5,%6,%7}, {%8,%9}, {%0,%1,%2,%3};"
                        : "+f"(acc[mi][ni][0]), "+f"(acc[mi][ni][1]),
                          "+f"(acc[mi][ni][2]), "+f"(acc[mi][ni][3])
                        : "r"(a[mi][0]), "r"(a[mi][1]), "r"(a[mi][2]), "r"(a[mi][3]),
                          "r"(b[ni][0]), "r"(b[ni][1]));
        }
        __syncthreads();
    }
    int m_base = mt * 128 + wm * 64;
    int n_base = vt * 128 + wn * 32;
#pragma unroll
    for (int mi = 0; mi < 4; mi++) {
#pragma unroll
        for (int ni = 0; ni < 4; ni++) {
            int row0 = m_base + mi * 16 + (lane >> 2);
            int col0 = n_base + ni * 8 + (lane & 3) * 2;
            float b0 = bias ? bias[col0] : 0.f;
            float b1 = bias ? bias[col0 + 1] : 0.f;
            float2 lo = make_float2(acc[mi][ni][0] + b0, acc[mi][ni][1] + b1);
            float2 hi = make_float2(acc[mi][ni][2] + b0, acc[mi][ni][3] + b1);
            *(float2*)(Cout + (size_t)row0 * Nout + col0) = lo;
            *(float2*)(Cout + (size_t)(row0 + 8) * Nout + col0) = hi;
        }
    }
}

// BN=256 mma (logits only) — R10 version, grid (M/128, Nout/256), 96KB smem.
__global__ __launch_bounds__(256) void mma_gemm256(
    const __nv_bfloat16* __restrict__ Abf, const __nv_bfloat16* __restrict__ Wbf,
    const float* __restrict__ bias, float* __restrict__ Cout,
    int Nout, int kchunks)
{
    extern __shared__ char dsm[];
    uint32_t sbase = smem_u32(dsm);
    uint32_t abase = (sbase + 1023u) & ~1023u;
    int tid = threadIdx.x;
    int wid = tid >> 5, lane = tid & 31;
    int wm = wid >> 2, wn = wid & 3;
    int mt = blockIdx.x, vt = blockIdx.y;
    int ld = kchunks * 64;
    const __nv_bfloat16* Arow = Abf + (size_t)mt * 128 * ld;
    const __nv_bfloat16* Wrow = Wbf + (size_t)vt * 256 * ld;
    float acc[4][8][4];
#pragma unroll
    for (int mi = 0; mi < 4; mi++)
#pragma unroll
        for (int ni = 0; ni < 8; ni++)
#pragma unroll
            for (int q = 0; q < 4; q++) acc[mi][ni][q] = 0.f;
    int lr = tid >> 3, lc16 = tid & 7;
    {
        uint32_t as = abase, bs = abase + 16384;
#pragma unroll
        for (int j = 0; j < 4; j++) {
            int r = lr + j * 32;
            uint32_t sw = ((uint32_t)(lc16 ^ (r & 7))) << 4;
            cp16(as + r * 128 + sw, Arow + (size_t)r * ld + lc16 * 8);
        }
#pragma unroll
        for (int j = 0; j < 8; j++) {
            int r = lr + j * 32;
            uint32_t sw = ((uint32_t)(lc16 ^ (r & 7))) << 4;
            cp16(bs + r * 128 + sw, Wrow + (size_t)r * ld + lc16 * 8);
        }
        asm volatile("cp.async.commit_group;");
    }
    for (int kc = 0; kc < kchunks; kc++) {
        int cur = kc & 1;
        if (kc < kchunks - 1) {
            uint32_t as = abase + (cur ^ 1) * 49152, bs = as + 16384;
            const __nv_bfloat16* Ak = Arow + (kc + 1) * 64;
            const __nv_bfloat16* Wk = Wrow + (kc + 1) * 64;
#pragma unroll
            for (int j = 0; j < 4; j++) {
                int r = lr + j * 32;
                uint32_t sw = ((uint32_t)(lc16 ^ (r & 7))) << 4;
                cp16(as + r * 128 + sw, Ak + (size_t)r * ld + lc16 * 8);
            }
#pragma unroll
            for (int j = 0; j < 8; j++) {
                int r = lr + j * 32;
                uint32_t sw = ((uint32_t)(lc16 ^ (r & 7))) << 4;
                cp16(bs + r * 128 + sw, Wk + (size_t)r * ld + lc16 * 8);
            }
            asm volatile("cp.async.commit_group;");
            asm volatile("cp.async.wait_group 1;");
        } else {
            asm volatile("cp.async.wait_group 0;");
        }
        __syncthreads();
        uint32_t as = abase + cur * 49152, bs = as + 16384;
#pragma unroll
        for (int ks = 0; ks < 4; ks++) {
            uint32_t a[4][4], b[8][2];
#pragma unroll
            for (int mi = 0; mi < 4; mi++) {
                int row = wm * 64 + mi * 16 + (lane & 15);
                int c16 = ks * 2 + (lane >> 4);
                uint32_t addr = as + row * 128 + (((uint32_t)(c16 ^ (row & 7))) << 4);
                asm volatile(
                    "ldmatrix.sync.aligned.m8n8.x4.shared.b16 {%0,%1,%2,%3}, [%4];"
                    : "=r"(a[mi][0]), "=r"(a[mi][1]), "=r"(a[mi][2]), "=r"(a[mi][3])
                    : "r"(addr));
            }
#pragma unroll
            for (int ni = 0; ni < 8; ni++) {
                int row = wn * 64 + ni * 8 + (lane & 7);
                int c16 = ks * 2 + ((lane >> 3) & 1);
                uint32_t addr = bs + row * 128 + (((uint32_t)(c16 ^ (row & 7))) << 4);
                asm volatile(
                    "ldmatrix.sync.aligned.m8n8.x2.shared.b16 {%0,%1}, [%2];"
                    : "=r"(b[ni][0]), "=r"(b[ni][1]) : "r"(addr));
            }
#pragma unroll
            for (int mi = 0; mi < 4; mi++)
#pragma unroll
                for (int ni = 0; ni < 8; ni++)
                    asm volatile(
                        "mma.sync.aligned.m16n8k16.row.col.f32.bf16.bf16.f32 "
                        "{%0,%1,%2,%3}, {%4,%5,%6,%7}, {%8,%9}, {%0,%1,%2,%3};"
                        : "+f"(acc[mi][ni][0]), "+f"(acc[mi][ni][1]),
                          "+f"(acc[mi][ni][2]), "+f"(acc[mi][ni][3])
                        : "r"(a[mi][0]), "r"(a[mi][1]), "r"(a[mi][2]), "r"(a[mi][3]),
                          "r"(b[ni][0]), "r"(b[ni][1]));
        }
        __syncthreads();
    }
    int m_base = mt * 128 + wm * 64;
    int n_base = vt * 256 + wn * 64;
#pragma unroll
    for (int mi = 0; mi < 4; mi++) {
#pragma unroll
        for (int ni = 0; ni < 8; ni++) {
            int row0 = m_base + mi * 16 + (lane >> 2);
            int col0 = n_base + ni * 8 + (lane & 3) * 2;
            float b0 = bias ? bias[col0] : 0.f;
            float b1 = bias ? bias[col0 + 1] : 0.f;
            float2 lo = make_float2(acc[mi][ni][0] + b0, acc[mi][ni][1] + b1);
            float2 hi = make_float2(acc[mi][ni][2] + b0, acc[mi][ni][3] + b1);
            *(float2*)(Cout + (size_t)row0 * Nout + col0) = lo;
            *(float2*)(Cout + (size_t)(row0 + 8) * Nout + col0) = hi;
        }
    }
}

// ---- encoder LSTM step body (batch-group 16, masked) ----
__device__ __forceinline__ void enc_step_body(
    int g, int jblk, const float* __restrict__ xproj, const float* __restrict__ Whh,
    const float* __restrict__ bias, const float* __restrict__ h_in,
    float* __restrict__ h_out, float* __restrict__ c, float* __restrict__ out,
    const int* __restrict__ lens, int t, float* hs)
{
    int tid = threadIdx.x;
    for (int i = tid; i < 8192; i += 256) {
        int b = i >> 9, k = i & 511;
        hs[i] = h_in[(g * 16 + b) * 512 + k];
    }
    __syncthreads();
    int wid = tid >> 5, lane = tid & 31;
    int j = jblk * 8 + wid;
    const float* wh = Whh + (size_t)j * 512 + lane;
    float acc[16][4];
#pragma unroll
    for (int b = 0; b < 16; b++)
#pragma unroll
        for (int q = 0; q < 4; q++) acc[b][q] = 0.f;
#pragma unroll 4
    for (int kk = 0; kk < 512; kk += 32) {
        float w0 = wh[kk], w1 = wh[262144 + kk];
        float w2 = wh[524288 + kk], w3 = wh[786432 + kk];
#pragma unroll
        for (int b = 0; b < 16; b++) {
            float hv = hs[b * 512 + kk + lane];
            acc[b][0] = fmaf(w0, hv, acc[b][0]);
            acc[b][1] = fmaf(w1, hv, acc[b][1]);
            acc[b][2] = fmaf(w2, hv, acc[b][2]);
            acc[b][3] = fmaf(w3, hv, acc[b][3]);
        }
    }
#pragma unroll
    for (int b = 0; b < 16; b++)
#pragma unroll
        for (int q = 0; q < 4; q++) acc[b][q] = warp_sum(acc[b][q]);
    if (lane < 16) {
        int b = lane, bb = g * 16 + b;
        const float* xp = xproj + (size_t)(bb * 64 + t) * 2048;
        float gi = acc[b][0] + xp[j]        + bias[j];
        float gf = acc[b][1] + xp[512 + j]  + bias[512 + j];
        float gg = acc[b][2] + xp[1024 + j] + bias[1024 + j];
        float go = acc[b][3] + xp[1536 + j] + bias[1536 + j];
        bool v = t < lens[bb];
        float c2 = sigf(gf) * c[bb * 512 + j] + sigf(gi) * tanhf(gg);
        float h2 = sigf(go) * tanhf(c2);
        h_out[bb * 512 + j] = v ? h2 : hs[b * 512 + j];
        if (v) c[bb * 512 + j] = c2;
        out[(size_t)(bb * 64 + t) * 512 + j] = v ? h2 : 0.f;
    }
}

__global__ __launch_bounds__(256) void enc_l0_persist(
    const float* __restrict__ xpF, const float* __restrict__ WhhF,
    const float* __restrict__ bF,
    const float* __restrict__ xpB, const float* __restrict__ WhhB,
    const float* __restrict__ bB,
    float* h0F, float* h1F, float* cF, float* outF,
    float* h0B, float* h1B, float* cB, float* outB,
    const int* __restrict__ lens)
{
    __shared__ float hs[8192];
    int g = blockIdx.x >> 6, jblk = blockIdx.x & 63;
    float *hiF = h0F, *hoF = h1F, *hiB = h0B, *hoB = h1B;
    unsigned bar = 0;
    for (int t = 0; t < 64; t++) {
        enc_step_body(g, jblk, xpF, WhhF, bF, hiF, hoF, cF, outF, lens, t, hs);
        __syncthreads();
        enc_step_body(g, jblk, xpB, WhhB, bB, hiB, hoB, cB, outB, lens, 63 - t, hs);
        gsync(++bar * 128u);
        float* tm;
        tm = hiF; hiF = hoF; hoF = tm;
        tm = hiB; hiB = hoB; hoB = tm;
    }
}

__global__ __launch_bounds__(256) void enc_layer_persist(
    const float* __restrict__ xp, const float* __restrict__ Whh,
    const float* __restrict__ bias,
    float* h0, float* h1, float* c, float* out, const int* __restrict__ lens)
{
    __shared__ float hs[8192];
    int g = blockIdx.x >> 6, jblk = blockIdx.x & 63;
    float *hi = h0, *ho = h1;
    unsigned bar = 0;
    for (int t = 0; t < 64; t++) {
        enc_step_body(g, jblk, xp, Whh, bias, hi, ho, c, out, lens, t, hs);
        gsync(++bar * 128u);
        float* tm = hi; hi = ho; ho = tm;
    }
}

// ---- decoder cell body (batch-group 16) ----
__device__ __forceinline__ void dec_cell_body(
    const float* __restrict__ x, const float* __restrict__ xproj, int t,
    const float* __restrict__ Wih, int wstride,
    const float* __restrict__ Whh, const float* __restrict__ bias,
    const float* __restrict__ h_in, float* __restrict__ h_out,
    float* __restrict__ c, int resid, float* sm)
{
    int g = blockIdx.x >> 6, jblk = blockIdx.x & 63;
    float* xs = sm;
    float* hs = sm + 8192;
    int tid = threadIdx.x;
    for (int i = tid; i < 8192; i += 256) {
        int b = i >> 9, k = i & 511;
        xs[i] = x[(g * 16 + b) * 512 + k];
        hs[i] = h_in[(g * 16 + b) * 512 + k];
    }
    __syncthreads();
    int wid = tid >> 5, lane = tid & 31;
    int j = jblk * 8 + wid;
    float acc[16][4];
#pragma unroll
    for (int b = 0; b < 16; b++)
#pragma unroll
        for (int q = 0; q < 4; q++) acc[b][q] = 0.f;
    const float* wi = Wih + (size_t)j * wstride + lane;
    size_t rs = (size_t)512 * wstride;
#pragma unroll 4
    for (int kk = 0; kk < 512; kk += 32) {
        float w0 = wi[kk], w1 = wi[rs + kk];
        float w2 = wi[2 * rs + kk], w3 = wi[3 * rs + kk];
#pragma unroll
        for (int b = 0; b < 16; b++) {
            float xv = xs[b * 512 + kk + lane];
            acc[b][0] = fmaf(w0, xv, acc[b][0]);
            acc[b][1] = fmaf(w1, xv, acc[b][1]);
            acc[b][2] = fmaf(w2, xv, acc[b][2]);
            acc[b][3] = fmaf(w3, xv, acc[b][3]);
        }
    }
    const float* wh = Whh + (size_t)j * 512 + lane;
#pragma unroll 4
    for (int kk = 0; kk < 512; kk += 32) {
        float w0 = wh[kk], w1 = wh[262144 + kk];
        float w2 = wh[524288 + kk], w3 = wh[786432 + kk];
#pragma unroll
        for (int b = 0; b < 16; b++) {
            float hv = hs[b * 512 + kk + lane];
            acc[b][0] = fmaf(w0, hv, acc[b][0]);
            acc[b][1] = fmaf(w1, hv, acc[b][1]);
            acc[b][2] = fmaf(w2, hv, acc[b][2]);
            acc[b][3] = fmaf(w3, hv, acc[b][3]);
        }
    }
#pragma unroll
    for (int b = 0; b < 16; b++)
#pragma unroll
        for (int q = 0; q < 4; q++) acc[b][q] = warp_sum(acc[b][q]);
    if (lane < 16) {
        int b = lane, bb = g * 16 + b;
        float gi = acc[b][0] + bias[j];
        float gf = acc[b][1] + bias[512 + j];
        float gg = acc[b][2] + bias[1024 + j];
        float go = acc[b][3] + bias[1536 + j];
        if (xproj) {
            const float* xp = xproj + (size_t)(bb * 64 + t) * 2048;
            gi += xp[j]; gf += xp[512 + j]; gg += xp[1024 + j]; go += xp[1536 + j];
        }
        float c2 = sigf(gf) * c[bb * 512 + j] + sigf(gi) * tanhf(gg);
        float h2 = sigf(go) * tanhf(c2);
        c[bb * 512 + j] = c2;
        h_out[bb * 512 + j] = h2 + (resid ? xs[b * 512 + j] : 0.f);
    }
}

__device__ __forceinline__ void attn_body(
    int t, const float* __restrict__ top, const float* __restrict__ enc_out,
    const float* __restrict__ encA, const int* __restrict__ lens,
    float* __restrict__ ctx, float* __restrict__ topctx,
    float* __restrict__ attn_out, float* sm)
{
    int b = blockIdx.x >> 2, part = blockIdx.x & 3;
    float* qs = sm;
    float* sc = sm + 512;
    int tid = threadIdx.x;
    for (int k = tid; k < 512; k += 256) qs[k] = top[b * 512 + k];
    __syncthreads();
    int wid = tid >> 5, lane = tid & 31;
    int len = lens[b];
#pragma unroll
    for (int si = 0; si < 8; si++) {
        int s = wid * 8 + si;
        const float* er = encA + (size_t)(b * 64 + s) * 512;
        float a = 0.f;
#pragma unroll
        for (int kk = 0; kk < 512; kk += 32) a = fmaf(er[kk + lane], qs[kk + lane], a);
        a = warp_sum(a);
        if (lane == 0) sc[s] = (s < len) ? a : -INFINITY;
    }
    __syncthreads();
    if (wid == 0) {
        float v1 = sc[lane], v2 = sc[lane + 32];
        float m = fmaxf(v1, v2);
#pragma unroll
        for (int o = 16; o > 0; o >>= 1) m = fmaxf(m, __shfl_xor_sync(0xffffffffu, m, o));
        float e1 = expf(v1 - m), e2 = expf(v2 - m);
        float inv = 1.f / warp_sum(e1 + e2);
        e1 *= inv; e2 *= inv;
        sc[lane] = e1; sc[lane + 32] = e2;
        if (part == 0) {
            size_t ao = (size_t)b * 4096 + (size_t)t * 64;
            attn_out[ao + lane] = e1;
            attn_out[ao + lane + 32] = e2;
        }
    }
    __syncthreads();
    size_t row = (size_t)(b * 64 + t) * 1024;
    int j0 = part * 128;
    if (tid < 128) {
        int j = j0 + tid;
        float a = 0.f;
#pragma unroll 8
        for (int s = 0; s < 64; s++)
            a = fmaf(sc[s], enc_out[(size_t)(b * 64 + s) * 512 + j], a);
        ctx[b * 512 + j] = a;
        topctx[row + 512 + j] = a;
        topctx[row + j] = qs[j];
    }
}

__global__ __launch_bounds__(256) void dec_persist(
    const float* __restrict__ dembxp,
    const float* __restrict__ dec0_wih, const float* __restrict__ dec0_whh,
    const float* __restrict__ dec0_b,
    const float* __restrict__ dec_wih, const float* __restrict__ dec_whh,
    const float* __restrict__ dec_b,
    float* dhA, float* dhB, float* dc, float* ctx,
    const float* __restrict__ enc_out, const float* __restrict__ encA,
    const int* __restrict__ lens, float* topctx, float* attn_out)
{
    extern __shared__ float sm[];
    float* hA = dhA;
    float* hB = dhB;
    unsigned bar = 0;
    for (int t = 0; t < 64; t++) {
        dec_cell_body(ctx, dembxp, t, dec0_wih + 512, 1024, dec0_whh, dec0_b,
                      hA, hB, dc, 0, sm);
        gsync(++bar * 128u);
        dec_cell_body(hB, nullptr, t, dec_wih, 512, dec_whh, dec_b,
                      hA + 16384, hB + 16384, dc + 16384, 0, sm);
        gsync(++bar * 128u);
        dec_cell_body(hB + 16384, nullptr, t, dec_wih + (size_t)2048 * 512, 512,
                      dec_whh + (size_t)2048 * 512, dec_b + 2048,
                      hA + 2 * 16384, hB + 2 * 16384, dc + 2 * 16384, 1, sm);
        gsync(++bar * 128u);
        dec_cell_body(hB + 2 * 16384, nullptr, t, dec_wih + (size_t)2 * 2048 * 512, 512,
                      dec_whh + (size_t)2 * 2048 * 512, dec_b + 2 * 2048,
                      hA + 3 * 16384, hB + 3 * 16384, dc + 3 * 16384, 1, sm);
        gsync(++bar * 128u);
        attn_body(t, hB + 3 * 16384, enc_out, encA, lens, ctx, topctx, attn_out, sm);
        gsync(++bar * 128u);
        float* tm = hA; hA = hB; hB = tm;
    }
}

extern "C" void kernel_launch(void* const* d_in, const int* in_sizes, int n_in,
                              void* d_out, int out_size) {
    const int*   src_tokens  = (const int*)d_in[0];
    const int*   src_lengths = (const int*)d_in[1];
    const int*   tgt_tokens  = (const int*)d_in[2];
    const float* enc_embed   = (const float*)d_in[3];
    const float* enc_l0_wih  = (const float*)d_in[4];
    const float* enc_l0_whh  = (const float*)d_in[5];
    const float* enc_l0_b    = (const float*)d_in[6];
    const float* proj_w      = (const float*)d_in[7];
    const float* proj_b      = (const float*)d_in[8];
    const float* enc_wih     = (const float*)d_in[9];
    const float* enc_whh     = (const float*)d_in[10];
    const float* enc_b       = (const float*)d_in[11];
    const float* dec_embed   = (const float*)d_in[12];
    const float* dec0_wih    = (const float*)d_in[13];
    const float* dec0_whh    = (const float*)d_in[14];
    const float* dec0_b      = (const float*)d_in[15];
    const float* dec_wih     = (const float*)d_in[16];
    const float* dec_whh     = (const float*)d_in[17];
    const float* dec_b       = (const float*)d_in[18];
    const float* attn_w      = (const float*)d_in[19];
    const float* out_w       = (const float*)d_in[20];
    const float* out_b       = (const float*)d_in[21];

    float* base = nullptr;
    cudaGetSymbolAddress((void**)&base, g_scratch);
    __nv_bfloat16* bfb = nullptr;
    cudaGetSymbolAddress((void**)&bfb, g_bf);
    unsigned* cntp = nullptr;
    cudaGetSymbolAddress((void**)&cntp, g_cnt);
    cudaFuncSetAttribute(mma_gemm,
                         cudaFuncAttributeMaxDynamicSharedMemorySize, 66560);
    cudaFuncSetAttribute(mma_gemm256,
                         cudaFuncAttributeMaxDynamicSharedMemorySize, 99328);
    cudaFuncSetAttribute(dec_persist,
                         cudaFuncAttributeMaxDynamicSharedMemorySize, 65536);

    float* emb    = base + OFF_EMB;
    float* demb   = base + OFF_DEMB;
    float* xp0f   = base + OFF_XP0F;
    float* xp0b   = base + OFF_XP0B;
    float* xp     = base + OFF_XP;
    float* ofbuf  = base + OFF_OF;
    float* obbuf  = base + OFF_OB;
    float* cat    = base + OFF_CAT;
    float* l1     = base + OFF_L1;
    float* l2     = base + OFF_L2;
    float* topctx = base + OFF_TOPCTX;
    float* h0     = base + OFF_H0;
    float* h1     = base + OFF_H1;
    float* cc     = base + OFF_CC;
    float* hb0    = base + OFF_HB0;
    float* hb1    = base + OFF_HB1;
    float* cb     = base + OFF_CB;
    float* dhA    = base + OFF_DHA;
    float* dhB    = base + OFF_DHB;
    float* dc     = base + OFF_DC;
    float* ctx    = base + OFF_CTX;
    float* encA   = base + OFF_ENCA;
    float* awt    = base + OFF_AWT;
    float* dembxp = base + OFF_DEMBXP;

    float* logits   = (float*)d_out;
    float* attn_out = (float*)d_out + ((size_t)2048 * 32000);

    split_w_g<<<32000, 256>>>(out_w, bfb + BF_W, 1024, 1024, 32000);

    embed_kernel<<<4096, 256>>>(src_tokens, enc_embed, emb, 2048 * 512);
    embed_kernel<<<4096, 256>>>(tgt_tokens, dec_embed, demb, 2048 * 512);

    split_a_g<<<1024, 256>>>(demb, bfb + BF_XA, 512, 512, 2048);
    split_w_g<<<1024, 256>>>(dec0_wih, bfb + BF_XW, 512, 1024, 2048);
    mma_gemm<<<dim3(16, 16), 256, 66560>>>(bfb + BF_XA, bfb + BF_XW, nullptr,
                                           dembxp, 2048, 24);

    split_a_g<<<1024, 256>>>(emb, bfb + BF_XA, 512, 512, 2048);
    split_w_g<<<1024, 256>>>(enc_l0_wih, bfb + BF_XW, 512, 512, 2048);
    mma_gemm<<<dim3(16, 16), 256, 66560>>>(bfb + BF_XA, bfb + BF_XW, nullptr,
                                           xp0f, 2048, 24);
    split_w_g<<<1024, 256>>>(enc_l0_wih + (size_t)2048 * 512, bfb + BF_XW,
                             512, 512, 2048);
    mma_gemm<<<dim3(16, 16), 256, 66560>>>(bfb + BF_XA, bfb + BF_XW, nullptr,
                                           xp0b, 2048, 24);

    cudaMemsetAsync(h0, 0, 16384 * 4);
    cudaMemsetAsync(cc, 0, 16384 * 4);
    cudaMemsetAsync(hb0, 0, 16384 * 4);
    cudaMemsetAsync(cb, 0, 16384 * 4);
    cudaMemsetAsync(cntp, 0, 4);
    enc_l0_persist<<<128, 256>>>(xp0f, enc_l0_whh, enc_l0_b,
                                 xp0b, enc_l0_whh + (size_t)2048 * 512, enc_l0_b + 2048,
                                 h0, h1, cc, ofbuf, hb0, hb1, cb, obbuf, src_lengths);
    add2_kernel<<<64, 256>>>(dhA, h0, hb0, 16384);
    add2_kernel<<<64, 256>>>(dc, cc, cb, 16384);

    concat2_kernel<<<8192, 256>>>(cat, ofbuf, obbuf, 2048 * 1024);
    split_a_g<<<2048, 256>>>(cat, bfb + BF_CT, 1024, 1024, 2048);
    split_w_g<<<512, 256>>>(proj_w, bfb + BF_PW, 1024, 1024, 512);
    mma_gemm<<<dim3(16, 4), 256, 66560>>>(bfb + BF_CT, bfb + BF_PW, proj_b,
                                          l1, 512, 48);

    float* cur = l1;
    float* nxt = l2;
    for (int i = 0; i < 3; i++) {
        split_a_g<<<1024, 256>>>(cur, bfb + BF_XA, 512, 512, 2048);
        split_w_g<<<1024, 256>>>(enc_wih + (size_t)i * 2048 * 512, bfb + BF_XW,
                                 512, 512, 2048);
        mma_gemm<<<dim3(16, 16), 256, 66560>>>(bfb + BF_XA, bfb + BF_XW, nullptr,
                                               xp, 2048, 24);
        cudaMemsetAsync(h0, 0, 16384 * 4);
        cudaMemsetAsync(cc, 0, 16384 * 4);
        cudaMemsetAsync(cntp, 0, 4);
        enc_layer_persist<<<128, 256>>>(xp, enc_whh + (size_t)i * 2048 * 512,
                                        enc_b + i * 2048, h0, h1, cc, nxt, src_lengths);
        if (i >= 1) addip_kernel<<<4096, 256>>>(nxt, cur, 2048 * 512);
        cudaMemcpyAsync(dhA + (size_t)(i + 1) * 16384, h0, 16384 * 4,
                        cudaMemcpyDeviceToDevice);
        cudaMemcpyAsync(dc + (size_t)(i + 1) * 16384, cc, 16384 * 4,
                        cudaMemcpyDeviceToDevice);
        float* tmp = cur; cur = nxt; nxt = tmp;
    }
    float* enc_out = cur;

    transpose512_kernel<<<1024, 256>>>(attn_w, awt);
    split_a_g<<<1024, 256>>>(enc_out, bfb + BF_XA, 512, 512, 2048);
    split_w_g<<<256, 256>>>(awt, bfb + BF_XW, 512, 512, 512);
    mma_gemm<<<dim3(16, 4), 256, 66560>>>(bfb + BF_XA, bfb + BF_XW, nullptr,
                                          encA, 512, 24);

    cudaMemsetAsync(ctx, 0, 16384 * 4);
    cudaMemsetAsync(cntp, 0, 4);
    dec_persist<<<128, 256, 65536>>>(dembxp, dec0_wih, dec0_whh, dec0_b,
                                     dec_wih, dec_whh, dec_b,
                                     dhA, dhB, dc, ctx, enc_out, encA,
                                     src_lengths, topctx, attn_out);

    split_a_g<<<2048, 256>>>(topctx, bfb + BF_A, 1024, 1024, 2048);
    mma_gemm256<<<dim3(16, 125), 256, 99328>>>(bfb + BF_A, bfb + BF_W, out_b,
                                               logits, 32000, 48);
}

// round 16
// speedup vs baseline: 1.1258x; 1.1258x over previous
#include <cuda_runtime.h>
#include <cuda_bf16.h>
#include <cstdint>
#include <cmath>

static __device__ float g_scratch[28u * 1024u * 1024u];
static __device__ __nv_bfloat16 g_bf[119u * 1024u * 1024u];
static __device__ unsigned g_cnt;

#define OFF_EMB     ((size_t)0)
#define OFF_DEMB    (OFF_EMB    + 2048*512)
#define OFF_XP0F    (OFF_DEMB   + 2048*512)
#define OFF_XP0B    (OFF_XP0F   + 2048*2048)
#define OFF_XP      (OFF_XP0B   + 2048*2048)
#define OFF_OF      (OFF_XP     + 2048*2048)
#define OFF_OB      (OFF_OF     + 2048*512)
#define OFF_CAT     (OFF_OB     + 2048*512)
#define OFF_L1      (OFF_CAT    + 2048*1024)
#define OFF_L2      (OFF_L1     + 2048*512)
#define OFF_TOPCTX  (OFF_L2     + 2048*512)
#define OFF_H0      (OFF_TOPCTX + 2048*1024)
#define OFF_H1      (OFF_H0   + 16384)
#define OFF_CC      (OFF_H1   + 16384)
#define OFF_HB0     (OFF_CC   + 16384)
#define OFF_HB1     (OFF_HB0  + 16384)
#define OFF_CB      (OFF_HB1  + 16384)
#define OFF_DHA     (OFF_CB   + 16384)
#define OFF_DHB     (OFF_DHA  + 4*16384)
#define OFF_DC      (OFF_DHB  + 4*16384)
#define OFF_CTX     (OFF_DC   + 4*16384)
#define OFF_ENCA    (OFF_CTX  + 16384)
#define OFF_AWT     (OFF_ENCA + 2048*512)
#define OFF_DEMBXP  (OFF_AWT  + 512*512)
#define OFF_END     (OFF_DEMBXP + 2048*2048)
static_assert(OFF_END <= (size_t)28u * 1024u * 1024u, "scratch overflow");

#define BF_W   ((size_t)0)
#define BF_A   (BF_W  + (size_t)32000 * 3072)
#define BF_XA  (BF_A  + (size_t)2048 * 3072)
#define BF_XW  (BF_XA + (size_t)2048 * 1536)
#define BF_CT  (BF_XW + (size_t)2048 * 1536)
#define BF_PW  (BF_CT + (size_t)2048 * 3072)
#define BF_END (BF_PW + (size_t)512 * 3072)
static_assert(BF_END <= (size_t)119u * 1024u * 1024u, "bf overflow");

__device__ __forceinline__ float warp_sum(float v) {
#pragma unroll
    for (int o = 16; o > 0; o >>= 1) v += __shfl_xor_sync(0xffffffffu, v, o);
    return v;
}
__device__ __forceinline__ float sigf(float x) { return 1.f / (1.f + expf(-x)); }
__device__ __forceinline__ uint32_t smem_u32(const void* p) {
    uint32_t a;
    asm("{ .reg .u64 t; cvta.to.shared.u64 t, %1; cvt.u32.u64 %0, t; }" : "=r"(a) : "l"(p));
    return a;
}
__device__ __forceinline__ void cp16(uint32_t d, const void* g) {
    asm volatile("cp.async.cg.shared.global [%0], [%1], 16;" :: "r"(d), "l"(g));
}
__device__ __forceinline__ void gsync(unsigned target) {
    __syncthreads();
    __threadfence();
    if (threadIdx.x == 0) {
        atomicAdd(&g_cnt, 1u);
        volatile unsigned* p = &g_cnt;
        while (*p < target) {}
        __threadfence();
    }
    __syncthreads();
}

__global__ void embed_kernel(const int* __restrict__ tok, const float* __restrict__ tab,
                             float* __restrict__ out, int total) {
    int idx = blockIdx.x * 256 + threadIdx.x;
    if (idx >= total) return;
    int row = idx >> 9, col = idx & 511;
    int t = tok[row];
    out[idx] = (t == 0) ? 0.f : tab[(size_t)t * 512 + col];
}
__global__ void concat2_kernel(float* __restrict__ dst, const float* __restrict__ a,
                               const float* __restrict__ b, int total) {
    int idx = blockIdx.x * 256 + threadIdx.x;
    if (idx >= total) return;
    int r = idx >> 10, cidx = idx & 1023;
    dst[idx] = (cidx < 512) ? a[r * 512 + cidx] : b[r * 512 + cidx - 512];
}
__global__ void add2_kernel(float* __restrict__ d, const float* __restrict__ a,
                            const float* __restrict__ b, int n) {
    int i = blockIdx.x * 256 + threadIdx.x;
    if (i < n) d[i] = a[i] + b[i];
}
__global__ void addip_kernel(float* __restrict__ d, const float* __restrict__ a, int n) {
    int i = blockIdx.x * 256 + threadIdx.x;
    if (i < n) d[i] += a[i];
}
__global__ void transpose512_kernel(const float* __restrict__ in, float* __restrict__ out) {
    int idx = blockIdx.x * 256 + threadIdx.x;
    int r = idx >> 9, c = idx & 511;
    out[(size_t)c * 512 + r] = in[idx];
}

// ---- vectorized split kernels ----
__device__ __forceinline__ void split4(float4 v, uint2& hiq, uint2& loq) {
    __nv_bfloat16 h0 = __float2bfloat16(v.x), h1 = __float2bfloat16(v.y);
    __nv_bfloat16 h2 = __float2bfloat16(v.z), h3 = __float2bfloat16(v.w);
    __nv_bfloat16 l0 = __float2bfloat16(v.x - __bfloat162float(h0));
    __nv_bfloat16 l1 = __float2bfloat16(v.y - __bfloat162float(h1));
    __nv_bfloat16 l2 = __float2bfloat16(v.z - __bfloat162float(h2));
    __nv_bfloat16 l3 = __float2bfloat16(v.w - __bfloat162float(h3));
    __nv_bfloat162 hp0 = __nv_bfloat162(h0, h1), hp1 = __nv_bfloat162(h2, h3);
    __nv_bfloat162 lp0 = __nv_bfloat162(l0, l1), lp1 = __nv_bfloat162(l2, l3);
    hiq.x = *(uint32_t*)&hp0; hiq.y = *(uint32_t*)&hp1;
    loq.x = *(uint32_t*)&lp0; loq.y = *(uint32_t*)&lp1;
}
__global__ void split_w_g(const float* __restrict__ in, __nv_bfloat16* __restrict__ out,
                          int K, int lds, long rows) {
    long idx = (long)blockIdx.x * 256 + threadIdx.x;
    int qpr = K >> 2;
    if (idx >= rows * qpr) return;
    long r = idx / qpr; int k = (int)(idx - r * qpr) * 4;
    float4 v = *(const float4*)(in + r * lds + k);
    uint2 hiq, loq;
    split4(v, hiq, loq);
    size_t base = (size_t)r * 3 * K;
    *(uint2*)(out + base + k) = hiq;
    *(uint2*)(out + base + K + k) = hiq;
    *(uint2*)(out + base + 2 * K + k) = loq;
}
__global__ void split_a_g(const float* __restrict__ in, __nv_bfloat16* __restrict__ out,
                          int K, int lds, long rows) {
    long idx = (long)blockIdx.x * 256 + threadIdx.x;
    int qpr = K >> 2;
    if (idx >= rows * qpr) return;
    long r = idx / qpr; int k = (int)(idx - r * qpr) * 4;
    float4 v = *(const float4*)(in + r * lds + k);
    uint2 hiq, loq;
    split4(v, hiq, loq);
    size_t base = (size_t)r * 3 * K;
    *(uint2*)(out + base + k) = hiq;
    *(uint2*)(out + base + K + k) = loq;
    *(uint2*)(out + base + 2 * K + k) = hiq;
}

// BN=128 mma — R8 version (all GEMMs).
__global__ __launch_bounds__(256) void mma_gemm(
    const __nv_bfloat16* __restrict__ Abf, const __nv_bfloat16* __restrict__ Wbf,
    const float* __restrict__ bias, float* __restrict__ Cout,
    int Nout, int kchunks)
{
    extern __shared__ char dsm[];
    uint32_t sbase = smem_u32(dsm);
    uint32_t abase = (sbase + 1023u) & ~1023u;
    int tid = threadIdx.x;
    int wid = tid >> 5, lane = tid & 31;
    int wm = wid >> 2, wn = wid & 3;
    int mt = blockIdx.x, vt = blockIdx.y;
    int ld = kchunks * 64;
    const __nv_bfloat16* Arow = Abf + (size_t)mt * 128 * ld;
    const __nv_bfloat16* Wrow = Wbf + (size_t)vt * 128 * ld;
    float acc[4][4][4];
#pragma unroll
    for (int mi = 0; mi < 4; mi++)
#pragma unroll
        for (int ni = 0; ni < 4; ni++)
#pragma unroll
            for (int q = 0; q < 4; q++) acc[mi][ni][q] = 0.f;
    int lr = tid >> 3, lc16 = tid & 7;
    {
        uint32_t as = abase, bs = abase + 16384;
#pragma unroll
        for (int j = 0; j < 4; j++) {
            int r = lr + j * 32;
            uint32_t sw = ((uint32_t)(lc16 ^ (r & 7))) << 4;
            cp16(as + r * 128 + sw, Arow + (size_t)r * ld + lc16 * 8);
            cp16(bs + r * 128 + sw, Wrow + (size_t)r * ld + lc16 * 8);
        }
        asm volatile("cp.async.commit_group;");
    }
    for (int kc = 0; kc < kchunks; kc++) {
        int cur = kc & 1;
        if (kc < kchunks - 1) {
            uint32_t as = abase + (cur ^ 1) * 32768, bs = as + 16384;
            const __nv_bfloat16* Ak = Arow + (kc + 1) * 64;
            const __nv_bfloat16* Wk = Wrow + (kc + 1) * 64;
#pragma unroll
            for (int j = 0; j < 4; j++) {
                int r = lr + j * 32;
                uint32_t sw = ((uint32_t)(lc16 ^ (r & 7))) << 4;
                cp16(as + r * 128 + sw, Ak + (size_t)r * ld + lc16 * 8);
                cp16(bs + r * 128 + sw, Wk + (size_t)r * ld + lc16 * 8);
            }
            asm volatile("cp.async.commit_group;");
            asm volatile("cp.async.wait_group 1;");
        } else {
            asm volatile("cp.async.wait_group 0;");
        }
        __syncthreads();
        uint32_t as = abase + cur * 32768, bs = as + 16384;
#pragma unroll
        for (int ks = 0; ks < 4; ks++) {
            uint32_t a[4][4], b[4][2];
#pragma unroll
            for (int mi = 0; mi < 4; mi++) {
                int row = wm * 64 + mi * 16 + (lane & 15);
                int c16 = ks * 2 + (lane >> 4);
                uint32_t addr = as + row * 128 + (((uint32_t)(c16 ^ (row & 7))) << 4);
                asm volatile(
                    "ldmatrix.sync.aligned.m8n8.x4.shared.b16 {%0,%1,%2,%3}, [%4];"
                    : "=r"(a[mi][0]), "=r"(a[mi][1]), "=r"(a[mi][2]), "=r"(a[mi][3])
                    : "r"(addr));
            }
#pragma unroll
            for (int ni = 0; ni < 4; ni++) {
                int row = wn * 32 + ni * 8 + (lane & 7);
                int c16 = ks * 2 + ((lane >> 3) & 1);
                uint32_t addr = bs + row * 128 + (((uint32_t)(c16 ^ (row & 7))) << 4);
                asm volatile(
                    "ldmatrix.sync.aligned.m8n8.x2.shared.b16 {%0,%1}, [%2];"
                    : "=r"(b[ni][0]), "=r"(b[ni][1]) : "r"(addr));
            }
#pragma unroll
            for (int mi = 0; mi < 4; mi++)
#pragma unroll
                for (int ni = 0; ni < 4; ni++)
                    asm volatile(
                        "mma.sync.aligned.m16n8k16.row.col.f32.bf16.bf16.f32 "
                        "{%0,%1,%2,%3}, {%4,%5,%6,%7}, {%8,%9}, {%0,%1,%2,%3};"
                        : "+f"(acc[mi][ni][0]), "+f"(acc[mi][ni][1]),
                          "+f"(acc[mi][ni][2]), "+f"(acc[mi][ni][3])
                        : "r"(a[mi][0]), "r"(a[mi][1]), "r"(a[mi][2]), "r"(a[mi][3]),
                          "r"(b[ni][0]), "r"(b[ni][1]));
        }
        __syncthreads();
    }
    int m_base = mt * 128 + wm * 64;
    int n_base = vt * 128 + wn * 32;
#pragma unroll
    for (int mi = 0; mi < 4; mi++) {
#pragma unroll
        for (int ni = 0; ni < 4; ni++) {
            int row0 = m_base + mi * 16 + (lane >> 2);
            int col0 = n_base + ni * 8 + (lane & 3) * 2;
            float b0 = bias ? bias[col0] : 0.f;
            float b1 = bias ? bias[col0 + 1] : 0.f;
            float2 lo = make_float2(acc[mi][ni][0] + b0, acc[mi][ni][1] + b1);
            float2 hi = make_float2(acc[mi][ni][2] + b0, acc[mi][ni][3] + b1);
            *(float2*)(Cout + (size_t)row0 * Nout + col0) = lo;
            *(float2*)(Cout + (size_t)(row0 + 8) * Nout + col0) = hi;
        }
    }
}

// ---- encoder LSTM step body: float4-staged smem ----
__device__ __forceinline__ void enc_step_body(
    int g, int jblk, const float* __restrict__ xproj, const float* __restrict__ Whh,
    const float* __restrict__ bias, const float* __restrict__ h_in,
    float* __restrict__ h_out, float* __restrict__ c, float* __restrict__ out,
    const int* __restrict__ lens, int t, float* hs)
{
    int tid = threadIdx.x;
    for (int i = tid * 4; i < 8192; i += 1024) {
        int b = i >> 9, k = i & 511;
        *(float4*)&hs[i] = *(const float4*)&h_in[(g * 16 + b) * 512 + k];
    }
    __syncthreads();
    int wid = tid >> 5, lane = tid & 31;
    int j = jblk * 8 + wid;
    const float* wh = Whh + (size_t)j * 512 + lane;
    float acc[16][4];
#pragma unroll
    for (int b = 0; b < 16; b++)
#pragma unroll
        for (int q = 0; q < 4; q++) acc[b][q] = 0.f;
#pragma unroll 4
    for (int kk = 0; kk < 512; kk += 32) {
        float w0 = wh[kk], w1 = wh[262144 + kk];
        float w2 = wh[524288 + kk], w3 = wh[786432 + kk];
#pragma unroll
        for (int b = 0; b < 16; b++) {
            float hv = hs[b * 512 + kk + lane];
            acc[b][0] = fmaf(w0, hv, acc[b][0]);
            acc[b][1] = fmaf(w1, hv, acc[b][1]);
            acc[b][2] = fmaf(w2, hv, acc[b][2]);
            acc[b][3] = fmaf(w3, hv, acc[b][3]);
        }
    }
#pragma unroll
    for (int b = 0; b < 16; b++)
#pragma unroll
        for (int q = 0; q < 4; q++) acc[b][q] = warp_sum(acc[b][q]);
    if (lane < 16) {
        int b = lane, bb = g * 16 + b;
        const float* xp = xproj + (size_t)(bb * 64 + t) * 2048;
        float gi = acc[b][0] + xp[j]        + bias[j];
        float gf = acc[b][1] + xp[512 + j]  + bias[512 + j];
        float gg = acc[b][2] + xp[1024 + j] + bias[1024 + j];
        float go = acc[b][3] + xp[1536 + j] + bias[1536 + j];
        bool v = t < lens[bb];
        float c2 = sigf(gf) * c[bb * 512 + j] + sigf(gi) * tanhf(gg);
        float h2 = sigf(go) * tanhf(c2);
        h_out[bb * 512 + j] = v ? h2 : hs[b * 512 + j];
        if (v) c[bb * 512 + j] = c2;
        out[(size_t)(bb * 64 + t) * 512 + j] = v ? h2 : 0.f;
    }
}

__global__ __launch_bounds__(256) void enc_l0_persist(
    const float* __restrict__ xpF, const float* __restrict__ WhhF,
    const float* __restrict__ bF,
    const float* __restrict__ xpB, const float* __restrict__ WhhB,
    const float* __restrict__ bB,
    float* h0F, float* h1F, float* cF, float* outF,
    float* h0B, float* h1B, float* cB, float* outB,
    const int* __restrict__ lens)
{
    __shared__ __align__(16) float hs[8192];
    int g = blockIdx.x >> 6, jblk = blockIdx.x & 63;
    float *hiF = h0F, *hoF = h1F, *hiB = h0B, *hoB = h1B;
    unsigned bar = 0;
    for (int t = 0; t < 64; t++) {
        enc_step_body(g, jblk, xpF, WhhF, bF, hiF, hoF, cF, outF, lens, t, hs);
        __syncthreads();
        enc_step_body(g, jblk, xpB, WhhB, bB, hiB, hoB, cB, outB, lens, 63 - t, hs);
        gsync(++bar * 128u);
        float* tm;
        tm = hiF; hiF = hoF; hoF = tm;
        tm = hiB; hiB = hoB; hoB = tm;
    }
}

__global__ __launch_bounds__(256) void enc_layer_persist(
    const float* __restrict__ xp, const float* __restrict__ Whh,
    const float* __restrict__ bias,
    float* h0, float* h1, float* c, float* out, const int* __restrict__ lens)
{
    __shared__ __align__(16) float hs[8192];
    int g = blockIdx.x >> 6, jblk = blockIdx.x & 63;
    float *hi = h0, *ho = h1;
    unsigned bar = 0;
    for (int t = 0; t < 64; t++) {
        enc_step_body(g, jblk, xp, Whh, bias, hi, ho, c, out, lens, t, hs);
        gsync(++bar * 128u);
        float* tm = hi; hi = ho; ho = tm;
    }
}

// ---- decoder cell body: float4-staged smem ----
__device__ __forceinline__ void dec_cell_body(
    const float* __restrict__ x, const float* __restrict__ xproj, int t,
    const float* __restrict__ Wih, int wstride,
    const float* __restrict__ Whh, const float* __restrict__ bias,
    const float* __restrict__ h_in, float* __restrict__ h_out,
    float* __restrict__ c, int resid, float* sm)
{
    int g = blockIdx.x >> 6, jblk = blockIdx.x & 63;
    float* xs = sm;
    float* hs = sm + 8192;
    int tid = threadIdx.x;
    for (int i = tid * 4; i < 8192; i += 1024) {
        int b = i >> 9, k = i & 511;
        size_t go = (size_t)(g * 16 + b) * 512 + k;
        *(float4*)&xs[i] = *(const float4*)&x[go];
        *(float4*)&hs[i] = *(const float4*)&h_in[go];
    }
    __syncthreads();
    int wid = tid >> 5, lane = tid & 31;
    int j = jblk * 8 + wid;
    float acc[16][4];
#pragma unroll
    for (int b = 0; b < 16; b++)
#pragma unroll
        for (int q = 0; q < 4; q++) acc[b][q] = 0.f;
    const float* wi = Wih + (size_t)j * wstride + lane;
    size_t rs = (size_t)512 * wstride;
#pragma unroll 4
    for (int kk = 0; kk < 512; kk += 32) {
        float w0 = wi[kk], w1 = wi[rs + kk];
        float w2 = wi[2 * rs + kk], w3 = wi[3 * rs + kk];
#pragma unroll
        for (int b = 0; b < 16; b++) {
            float xv = xs[b * 512 + kk + lane];
            acc[b][0] = fmaf(w0, xv, acc[b][0]);
            acc[b][1] = fmaf(w1, xv, acc[b][1]);
            acc[b][2] = fmaf(w2, xv, acc[b][2]);
            acc[b][3] = fmaf(w3, xv, acc[b][3]);
        }
    }
    const float* wh = Whh + (size_t)j * 512 + lane;
#pragma unroll 4
    for (int kk = 0; kk < 512; kk += 32) {
        float w0 = wh[kk], w1 = wh[262144 + kk];
        float w2 = wh[524288 + kk], w3 = wh[786432 + kk];
#pragma unroll
        for (int b = 0; b < 16; b++) {
            float hv = hs[b * 512 + kk + lane];
            acc[b][0] = fmaf(w0, hv, acc[b][0]);
            acc[b][1] = fmaf(w1, hv, acc[b][1]);
            acc[b][2] = fmaf(w2, hv, acc[b][2]);
            acc[b][3] = fmaf(w3, hv, acc[b][3]);
        }
    }
#pragma unroll
    for (int b = 0; b < 16; b++)
#pragma unroll
        for (int q = 0; q < 4; q++) acc[b][q] = warp_sum(acc[b][q]);
    if (lane < 16) {
        int b = lane, bb = g * 16 + b;
        float gi = acc[b][0] + bias[j];
        float gf = acc[b][1] + bias[512 + j];
        float gg = acc[b][2] + bias[1024 + j];
        float go = acc[b][3] + bias[1536 + j];
        if (xproj) {
            const float* xp = xproj + (size_t)(bb * 64 + t) * 2048;
            gi += xp[j]; gf += xp[512 + j]; gg += xp[1024 + j]; go += xp[1536 + j];
        }
        float c2 = sigf(gf) * c[bb * 512 + j] + sigf(gi) * tanhf(gg);
        float h2 = sigf(go) * tanhf(c2);
        c[bb * 512 + j] = c2;
        h_out[bb * 512 + j] = h2 + (resid ? xs[b * 512 + j] : 0.f);
    }
}

__device__ __forceinline__ void attn_body(
    int t, const float* __restrict__ top, const float* __restrict__ enc_out,
    const float* __restrict__ encA, const int* __restrict__ lens,
    float* __restrict__ ctx, float* __restrict__ topctx,
    float* __restrict__ attn_out, float* sm)
{
    int b = blockIdx.x >> 2, part = blockIdx.x & 3;
    float* qs = sm;
    float* sc = sm + 512;
    int tid = threadIdx.x;
    if (tid < 128)
        *(float4*)&qs[tid * 4] = *(const float4*)&top[b * 512 + tid * 4];
    __syncthreads();
    int wid = tid >> 5, lane = tid & 31;
    int len = lens[b];
#pragma unroll
    for (int si = 0; si < 8; si++) {
        int s = wid * 8 + si;
        const float* er = encA + (size_t)(b * 64 + s) * 512;
        float a = 0.f;
#pragma unroll
        for (int kk = 0; kk < 512; kk += 32) a = fmaf(er[kk + lane], qs[kk + lane], a);
        a = warp_sum(a);
        if (lane == 0) sc[s] = (s < len) ? a : -INFINITY;
    }
    __syncthreads();
    if (wid == 0) {
        float v1 = sc[lane], v2 = sc[lane + 32];
        float m = fmaxf(v1, v2);
#pragma unroll
        for (int o = 16; o > 0; o >>= 1) m = fmaxf(m, __shfl_xor_sync(0xffffffffu, m, o));
        float e1 = expf(v1 - m), e2 = expf(v2 - m);
        float inv = 1.f / warp_sum(e1 + e2);
        e1 *= inv; e2 *= inv;
        sc[lane] = e1; sc[lane + 32] = e2;
        if (part == 0) {
            size_t ao = (size_t)b * 4096 + (size_t)t * 64;
            attn_out[ao + lane] = e1;
            attn_out[ao + lane + 32] = e2;
        }
    }
    __syncthreads();
    size_t row = (size_t)(b * 64 + t) * 1024;
    int j0 = part * 128;
    if (tid < 128) {
        int j = j0 + tid;
        float a = 0.f;
#pragma unroll 8
        for (int s = 0; s < 64; s++)
            a = fmaf(sc[s], enc_out[(size_t)(b * 64 + s) * 512 + j], a);
        ctx[b * 512 + j] = a;
        topctx[row + 512 + j] = a;
        topctx[row + j] = qs[j];
    }
}

__global__ __launch_bounds__(256) void dec_persist(
    const float* __restrict__ dembxp,
    const float* __restrict__ dec0_wih, const float* __restrict__ dec0_whh,
    const float* __restrict__ dec0_b,
    const float* __restrict__ dec_wih, const float* __restrict__ dec_whh,
    const float* __restrict__ dec_b,
    float* dhA, float* dhB, float* dc, float* ctx,
    const float* __restrict__ enc_out, const float* __restrict__ encA,
    const int* __restrict__ lens, float* topctx, float* attn_out)
{
    extern __shared__ __align__(16) float sm[];
    float* hA = dhA;
    float* hB = dhB;
    unsigned bar = 0;
    for (int t = 0; t < 64; t++) {
        dec_cell_body(ctx, dembxp, t, dec0_wih + 512, 1024, dec0_whh, dec0_b,
                      hA, hB, dc, 0, sm);
        gsync(++bar * 128u);
        dec_cell_body(hB, nullptr, t, dec_wih, 512, dec_whh, dec_b,
                      hA + 16384, hB + 16384, dc + 16384, 0, sm);
        gsync(++bar * 128u);
        dec_cell_body(hB + 16384, nullptr, t, dec_wih + (size_t)2048 * 512, 512,
                      dec_whh + (size_t)2048 * 512, dec_b + 2048,
                      hA + 2 * 16384, hB + 2 * 16384, dc + 2 * 16384, 1, sm);
        gsync(++bar * 128u);
        dec_cell_body(hB + 2 * 16384, nullptr, t, dec_wih + (size_t)2 * 2048 * 512, 512,
                      dec_whh + (size_t)2 * 2048 * 512, dec_b + 2 * 2048,
                      hA + 3 * 16384, hB + 3 * 16384, dc + 3 * 16384, 1, sm);
        gsync(++bar * 128u);
        attn_body(t, hB + 3 * 16384, enc_out, encA, lens, ctx, topctx, attn_out, sm);
        gsync(++bar * 128u);
        float* tm = hA; hA = hB; hB = tm;
    }
}

extern "C" void kernel_launch(void* const* d_in, const int* in_sizes, int n_in,
                              void* d_out, int out_size) {
    const int*   src_tokens  = (const int*)d_in[0];
    const int*   src_lengths = (const int*)d_in[1];
    const int*   tgt_tokens  = (const int*)d_in[2];
    const float* enc_embed   = (const float*)d_in[3];
    const float* enc_l0_wih  = (const float*)d_in[4];
    const float* enc_l0_whh  = (const float*)d_in[5];
    const float* enc_l0_b    = (const float*)d_in[6];
    const float* proj_w      = (const float*)d_in[7];
    const float* proj_b      = (const float*)d_in[8];
    const float* enc_wih     = (const float*)d_in[9];
    const float* enc_whh     = (const float*)d_in[10];
    const float* enc_b       = (const float*)d_in[11];
    const float* dec_embed   = (const float*)d_in[12];
    const float* dec0_wih    = (const float*)d_in[13];
    const float* dec0_whh    = (const float*)d_in[14];
    const float* dec0_b      = (const float*)d_in[15];
    const float* dec_wih     = (const float*)d_in[16];
    const float* dec_whh     = (const float*)d_in[17];
    const float* dec_b       = (const float*)d_in[18];
    const float* attn_w      = (const float*)d_in[19];
    const float* out_w       = (const float*)d_in[20];
    const float* out_b       = (const float*)d_in[21];

    float* base = nullptr;
    cudaGetSymbolAddress((void**)&base, g_scratch);
    __nv_bfloat16* bfb = nullptr;
    cudaGetSymbolAddress((void**)&bfb, g_bf);
    unsigned* cntp = nullptr;
    cudaGetSymbolAddress((void**)&cntp, g_cnt);
    cudaFuncSetAttribute(mma_gemm,
                         cudaFuncAttributeMaxDynamicSharedMemorySize, 66560);
    cudaFuncSetAttribute(dec_persist,
                         cudaFuncAttributeMaxDynamicSharedMemorySize, 65536);

    float* emb    = base + OFF_EMB;
    float* demb   = base + OFF_DEMB;
    float* xp0f   = base + OFF_XP0F;
    float* xp0b   = base + OFF_XP0B;
    float* xp     = base + OFF_XP;
    float* ofbuf  = base + OFF_OF;
    float* obbuf  = base + OFF_OB;
    float* cat    = base + OFF_CAT;
    float* l1     = base + OFF_L1;
    float* l2     = base + OFF_L2;
    float* topctx = base + OFF_TOPCTX;
    float* h0     = base + OFF_H0;
    float* h1     = base + OFF_H1;
    float* cc     = base + OFF_CC;
    float* hb0    = base + OFF_HB0;
    float* hb1    = base + OFF_HB1;
    float* cb     = base + OFF_CB;
    float* dhA    = base + OFF_DHA;
    float* dhB    = base + OFF_DHB;
    float* dc     = base + OFF_DC;
    float* ctx    = base + OFF_CTX;
    float* encA   = base + OFF_ENCA;
    float* awt    = base + OFF_AWT;
    float* dembxp = base + OFF_DEMBXP;

    float* logits   = (float*)d_out;
    float* attn_out = (float*)d_out + ((size_t)2048 * 32000);

    split_w_g<<<32000, 256>>>(out_w, bfb + BF_W, 1024, 1024, 32000);

    embed_kernel<<<4096, 256>>>(src_tokens, enc_embed, emb, 2048 * 512);
    embed_kernel<<<4096, 256>>>(tgt_tokens, dec_embed, demb, 2048 * 512);

    split_a_g<<<1024, 256>>>(demb, bfb + BF_XA, 512, 512, 2048);
    split_w_g<<<1024, 256>>>(dec0_wih, bfb + BF_XW, 512, 1024, 2048);
    mma_gemm<<<dim3(16, 16), 256, 66560>>>(bfb + BF_XA, bfb + BF_XW, nullptr,
                                           dembxp, 2048, 24);

    split_a_g<<<1024, 256>>>(emb, bfb + BF_XA, 512, 512, 2048);
    split_w_g<<<1024, 256>>>(enc_l0_wih, bfb + BF_XW, 512, 512, 2048);
    mma_gemm<<<dim3(16, 16), 256, 66560>>>(bfb + BF_XA, bfb + BF_XW, nullptr,
                                           xp0f, 2048, 24);
    split_w_g<<<1024, 256>>>(enc_l0_wih + (size_t)2048 * 512, bfb + BF_XW,
                             512, 512, 2048);
    mma_gemm<<<dim3(16, 16), 256, 66560>>>(bfb + BF_XA, bfb + BF_XW, nullptr,
                                           xp0b, 2048, 24);

    cudaMemsetAsync(h0, 0, 16384 * 4);
    cudaMemsetAsync(cc, 0, 16384 * 4);
    cudaMemsetAsync(hb0, 0, 16384 * 4);
    cudaMemsetAsync(cb, 0, 16384 * 4);
    cudaMemsetAsync(cntp, 0, 4);
    enc_l0_persist<<<128, 256>>>(xp0f, enc_l0_whh, enc_l0_b,
                                 xp0b, enc_l0_whh + (size_t)2048 * 512, enc_l0_b + 2048,
                                 h0, h1, cc, ofbuf, hb0, hb1, cb, obbuf, src_lengths);
    add2_kernel<<<64, 256>>>(dhA, h0, hb0, 16384);
    add2_kernel<<<64, 256>>>(dc, cc, cb, 16384);

    concat2_kernel<<<8192, 256>>>(cat, ofbuf, obbuf, 2048 * 1024);
    split_a_g<<<2048, 256>>>(cat, bfb + BF_CT, 1024, 1024, 2048);
    split_w_g<<<512, 256>>>(proj_w, bfb + BF_PW, 1024, 1024, 512);
    mma_gemm<<<dim3(16, 4), 256, 66560>>>(bfb + BF_CT, bfb + BF_PW, proj_b,
                                          l1, 512, 48);

    float* cur = l1;
    float* nxt = l2;
    for (int i = 0; i < 3; i++) {
        split_a_g<<<1024, 256>>>(cur, bfb + BF_XA, 512, 512, 2048);
        split_w_g<<<1024, 256>>>(enc_wih + (size_t)i * 2048 * 512, bfb + BF_XW,
                                 512, 512, 2048);
        mma_gemm<<<dim3(16, 16), 256, 66560>>>(bfb + BF_XA, bfb + BF_XW, nullptr,
                                               xp, 2048, 24);
        cudaMemsetAsync(h0, 0, 16384 * 4);
        cudaMemsetAsync(cc, 0, 16384 * 4);
        cudaMemsetAsync(cntp, 0, 4);
        enc_layer_persist<<<128, 256>>>(xp, enc_whh + (size_t)i * 2048 * 512,
                                        enc_b + i * 2048, h0, h1, cc, nxt, src_lengths);
        if (i >= 1) addip_kernel<<<4096, 256>>>(nxt, cur, 2048 * 512);
        cudaMemcpyAsync(dhA + (size_t)(i + 1) * 16384, h0, 16384 * 4,
                        cudaMemcpyDeviceToDevice);
        cudaMemcpyAsync(dc + (size_t)(i + 1) * 16384, cc, 16384 * 4,
                        cudaMemcpyDeviceToDevice);
        float* tmp = cur; cur = nxt; nxt = tmp;
    }
    float* enc_out = cur;

    transpose512_kernel<<<1024, 256>>>(attn_w, awt);
    split_a_g<<<1024, 256>>>(enc_out, bfb + BF_XA, 512, 512, 2048);
    split_w_g<<<256, 256>>>(awt, bfb + BF_XW, 512, 512, 512);
    mma_gemm<<<dim3(16, 4), 256, 66560>>>(bfb + BF_XA, bfb + BF_XW, nullptr,
                                          encA, 512, 24);

    cudaMemsetAsync(ctx, 0, 16384 * 4);
    cudaMemsetAsync(cntp, 0, 4);
    dec_persist<<<128, 256, 65536>>>(dembxp, dec0_wih, dec0_whh, dec0_b,
                                     dec_wih, dec_whh, dec_b,
                                     dhA, dhB, dc, ctx, enc_out, encA,
                                     src_lengths, topctx, attn_out);

    split_a_g<<<2048, 256>>>(topctx, bfb + BF_A, 1024, 1024, 2048);
    mma_gemm<<<dim3(16, 250), 256, 66560>>>(bfb + BF_A, bfb + BF_W, out_b,
                                            logits, 32000, 48);
}